// round 2
// baseline (speedup 1.0000x reference)
#include <cuda_runtime.h>
#include <math.h>

#define NB 2
#define NS 2048
#define ND 1024
#define NH 16
#define HDIM 64
#define MROWS (NB*NS)

// Scratch (device globals; no allocations allowed)
__device__ float g_q[NB*NH*NS*HDIM];    // [b*H+h][s][e]
__device__ float g_k[NB*NH*NS*HDIM];
__device__ float g_v[NB*NH*NS*HDIM];
__device__ float g_ctx[NB*NS*ND];       // [b][s][h*64+e]

struct GArgs { const float* A; const float* W; const float* bias; float* C; };

// C[m][n] = sum_k A[m,k] * W[n,k] + bias[n]
// headmode=1: scatter cols to head layout [b*H+h][s][e]; headmode=0: row-major [M,N]
__global__ __launch_bounds__(256) void sgemm_k(GArgs a0, GArgs a1, GArgs a2, int headmode)
{
    GArgs g = (blockIdx.z == 0) ? a0 : (blockIdx.z == 1) ? a1 : a2;
    __shared__ float As[8][128];
    __shared__ float Bs[8][128];
    const int K = ND;
    int tid = threadIdx.x;
    int mBase = blockIdx.y * 128, nBase = blockIdx.x * 128;
    int lr = tid >> 1, lk = (tid & 1) * 4;
    const float* Ap = g.A + (size_t)(mBase + lr) * K + lk;
    const float* Wp = g.W + (size_t)(nBase + lr) * K + lk;
    int tr = tid >> 4, tc = tid & 15;

    float acc[8][8];
#pragma unroll
    for (int i = 0; i < 8; i++)
#pragma unroll
        for (int j = 0; j < 8; j++) acc[i][j] = 0.f;

    for (int k0 = 0; k0 < K; k0 += 8) {
        float4 av = *(const float4*)(Ap + k0);
        float4 wv = *(const float4*)(Wp + k0);
        __syncthreads();
        As[lk + 0][lr] = av.x; As[lk + 1][lr] = av.y; As[lk + 2][lr] = av.z; As[lk + 3][lr] = av.w;
        Bs[lk + 0][lr] = wv.x; Bs[lk + 1][lr] = wv.y; Bs[lk + 2][lr] = wv.z; Bs[lk + 3][lr] = wv.w;
        __syncthreads();
#pragma unroll
        for (int kk = 0; kk < 8; kk++) {
            float ra[8], rb[8];
#pragma unroll
            for (int i = 0; i < 8; i++) ra[i] = As[kk][tr * 8 + i];
#pragma unroll
            for (int j = 0; j < 8; j++) rb[j] = Bs[kk][tc * 8 + j];
#pragma unroll
            for (int i = 0; i < 8; i++)
#pragma unroll
                for (int j = 0; j < 8; j++)
                    acc[i][j] = fmaf(ra[i], rb[j], acc[i][j]);
        }
    }

#pragma unroll
    for (int i = 0; i < 8; i++) {
        int m = mBase + tr * 8 + i;
#pragma unroll
        for (int j4 = 0; j4 < 8; j4 += 4) {
            int n0 = nBase + tc * 8 + j4;
            float4 bv = *(const float4*)(g.bias + n0);
            float4 r;
            r.x = acc[i][j4 + 0] + bv.x;
            r.y = acc[i][j4 + 1] + bv.y;
            r.z = acc[i][j4 + 2] + bv.z;
            r.w = acc[i][j4 + 3] + bv.w;
            if (headmode) {
                int b = m >> 11, s = m & (NS - 1);
                int h = n0 >> 6, e = n0 & 63;
                *(float4*)(g.C + ((size_t)((b * NH + h) * NS + s)) * HDIM + e) = r;
            } else {
                *(float4*)(g.C + (size_t)m * ND + n0) = r;
            }
        }
    }
}

// Flash attention: BQ=64, BKV=64, hd=64, 128 threads (16x8 thread grid, 4x8 microtile)
__global__ __launch_bounds__(128) void attn_k(const float* __restrict__ gq,
                                              const float* __restrict__ gk,
                                              const float* __restrict__ gv,
                                              const int* __restrict__ mask,
                                              float* __restrict__ ctx)
{
    extern __shared__ float sm[];
    float* Qs  = sm;               // [64][65]
    float* KPs = sm + 64 * 65;     // [64][65]  (K tile, then reused for P)
    float* Vs  = sm + 2 * 64 * 65; // [64][64]
    __shared__ int maskS[64];

    int tid = threadIdx.x;
    int ty = tid >> 3, tx = tid & 7;
    int qt = blockIdx.x;           // 0..31 query tile
    int bh = blockIdx.y;           // 0..31 (b*16+h)
    int b = bh >> 4;
    int h = bh & 15;

    size_t headoff = (size_t)bh * NS * HDIM;

    // Load Q tile, pre-scaled by 1/sqrt(64)=0.125 (exact power of 2)
    {
        const float* qp = gq + headoff + (size_t)qt * 64 * HDIM;
        for (int i = tid; i < 64 * 16; i += 128) {
            int r = i >> 4, e4 = (i & 15) << 2;
            float4 v = *(const float4*)(qp + r * HDIM + e4);
            float* d = Qs + r * 65 + e4;
            d[0] = v.x * 0.125f; d[1] = v.y * 0.125f; d[2] = v.z * 0.125f; d[3] = v.w * 0.125f;
        }
    }

    float mI[4], lI[4], O[4][8];
#pragma unroll
    for (int i = 0; i < 4; i++) {
        mI[i] = -INFINITY; lI[i] = 0.f;
#pragma unroll
        for (int j = 0; j < 8; j++) O[i][j] = 0.f;
    }

    const int* mrow = mask + (size_t)b * NS;

    for (int kt = 0; kt < NS / 64; kt++) {
        __syncthreads();  // prev iter's reads of KPs/Vs done (also covers Q load on iter 0)
        const float* kp = gk + headoff + (size_t)kt * 64 * HDIM;
        const float* vp = gv + headoff + (size_t)kt * 64 * HDIM;
        for (int i = tid; i < 1024; i += 128) {
            int r = i >> 4, e4 = (i & 15) << 2;
            float4 kv = *(const float4*)(kp + r * HDIM + e4);
            float* kd = KPs + r * 65 + e4;
            kd[0] = kv.x; kd[1] = kv.y; kd[2] = kv.z; kd[3] = kv.w;
            float4 vv = *(const float4*)(vp + r * HDIM + e4);
            *(float4*)(Vs + r * 64 + e4) = vv;
        }
        if (tid < 64) maskS[tid] = mrow[kt * 64 + tid];
        __syncthreads();

        // S = Q K^T (scaled already)
        float s[4][8];
#pragma unroll
        for (int i = 0; i < 4; i++)
#pragma unroll
            for (int j = 0; j < 8; j++) s[i][j] = 0.f;

        for (int e = 0; e < 64; e++) {
            float qf[4], kf[8];
#pragma unroll
            for (int i = 0; i < 4; i++) qf[i] = Qs[(4 * ty + i) * 65 + e];
#pragma unroll
            for (int j = 0; j < 8; j++) kf[j] = KPs[(8 * tx + j) * 65 + e];
#pragma unroll
            for (int i = 0; i < 4; i++)
#pragma unroll
                for (int j = 0; j < 8; j++)
                    s[i][j] = fmaf(qf[i], kf[j], s[i][j]);
        }

        // mask (nonzero -> -9e9, matching reference exactly)
#pragma unroll
        for (int j = 0; j < 8; j++) {
            if (maskS[8 * tx + j]) {
#pragma unroll
                for (int i = 0; i < 4; i++) s[i][j] = -9e9f;
            }
        }

        // online softmax per q-row (row spans the 8 tx lanes)
#pragma unroll
        for (int i = 0; i < 4; i++) {
            float mt = s[i][0];
#pragma unroll
            for (int j = 1; j < 8; j++) mt = fmaxf(mt, s[i][j]);
            mt = fmaxf(mt, __shfl_xor_sync(0xffffffffu, mt, 1));
            mt = fmaxf(mt, __shfl_xor_sync(0xffffffffu, mt, 2));
            mt = fmaxf(mt, __shfl_xor_sync(0xffffffffu, mt, 4));
            float mNew = fmaxf(mI[i], mt);
            float f = __expf(mI[i] - mNew);
            float rs = 0.f;
#pragma unroll
            for (int j = 0; j < 8; j++) { s[i][j] = __expf(s[i][j] - mNew); rs += s[i][j]; }
            rs += __shfl_xor_sync(0xffffffffu, rs, 1);
            rs += __shfl_xor_sync(0xffffffffu, rs, 2);
            rs += __shfl_xor_sync(0xffffffffu, rs, 4);
            lI[i] = lI[i] * f + rs;
#pragma unroll
            for (int j = 0; j < 8; j++) O[i][j] *= f;
            mI[i] = mNew;
        }

        __syncthreads();  // all K reads done before overwriting with P
#pragma unroll
        for (int i = 0; i < 4; i++)
#pragma unroll
            for (int j = 0; j < 8; j++)
                KPs[(4 * ty + i) * 65 + 8 * tx + j] = s[i][j];
        __syncthreads();

        // O += P V
        for (int k = 0; k < 64; k++) {
            float pf[4], vf[8];
#pragma unroll
            for (int i = 0; i < 4; i++) pf[i] = KPs[(4 * ty + i) * 65 + k];
#pragma unroll
            for (int j = 0; j < 8; j++) vf[j] = Vs[k * 64 + 8 * tx + j];
#pragma unroll
            for (int i = 0; i < 4; i++)
#pragma unroll
                for (int j = 0; j < 8; j++)
                    O[i][j] = fmaf(pf[i], vf[j], O[i][j]);
        }
    }

    // normalize + write context in [b][s][h*64+e] layout
#pragma unroll
    for (int i = 0; i < 4; i++) {
        float inv = 1.f / lI[i];
        int srow = qt * 64 + 4 * ty + i;
        float* op = ctx + ((size_t)(b * NS + srow)) * ND + h * HDIM + 8 * tx;
        float4 r0 = make_float4(O[i][0] * inv, O[i][1] * inv, O[i][2] * inv, O[i][3] * inv);
        float4 r1 = make_float4(O[i][4] * inv, O[i][5] * inv, O[i][6] * inv, O[i][7] * inv);
        *(float4*)op = r0;
        *(float4*)(op + 4) = r1;
    }
}

extern "C" void kernel_launch(void* const* d_in, const int* in_sizes, int n_in,
                              void* d_out, int out_size)
{
    const float* q  = (const float*)d_in[0];
    const float* k  = (const float*)d_in[1];
    const float* v  = (const float*)d_in[2];
    const int* mask = (const int*)d_in[3];
    const float* Wq = (const float*)d_in[4];
    const float* bq = (const float*)d_in[5];
    const float* Wk = (const float*)d_in[6];
    const float* bk = (const float*)d_in[7];
    const float* Wv = (const float*)d_in[8];
    const float* bv = (const float*)d_in[9];
    const float* Wo = (const float*)d_in[10];
    const float* bo = (const float*)d_in[11];
    float* out = (float*)d_out;

    float *gq_d, *gk_d, *gv_d, *gctx_d;
    cudaGetSymbolAddress((void**)&gq_d, g_q);
    cudaGetSymbolAddress((void**)&gk_d, g_k);
    cudaGetSymbolAddress((void**)&gv_d, g_v);
    cudaGetSymbolAddress((void**)&gctx_d, g_ctx);

    const int smem_attn = (2 * 64 * 65 + 64 * 64) * (int)sizeof(float);  // 49664
    cudaFuncSetAttribute(attn_k, cudaFuncAttributeMaxDynamicSharedMemorySize, smem_attn);

    // QKV projections (z-fused)
    GArgs aq{q, Wq, bq, gq_d};
    GArgs ak{k, Wk, bk, gk_d};
    GArgs av{v, Wv, bv, gv_d};
    sgemm_k<<<dim3(ND / 128, MROWS / 128, 3), 256>>>(aq, ak, av, 1);

    // attention
    attn_k<<<dim3(NS / 64, NB * NH), 128, smem_attn>>>(gq_d, gk_d, gv_d, mask, gctx_d);

    // output projection
    GArgs ao{gctx_d, Wo, bo, out};
    sgemm_k<<<dim3(ND / 128, MROWS / 128, 1), 256>>>(ao, ao, ao, 0);
}

// round 4
// speedup vs baseline: 1.3451x; 1.3451x over previous
#include <cuda_runtime.h>
#include <cuda_bf16.h>
#include <math.h>
#include <stdint.h>

#define NB 2
#define NS 2048
#define ND 1024
#define NH 16
#define HDIM 64
#define MROWS (NB*NS)

// Scratch (device globals; no allocations allowed)
__device__ float g_q[NB*NH*NS*HDIM];    // [b*H+h][s][e]
__device__ float g_k[NB*NH*NS*HDIM];
__device__ float g_v[NB*NH*NS*HDIM];
__device__ float g_ctx[NB*NS*ND];       // [b][s][h*64+e]

struct GArgs { const float* A; const float* W; const float* bias; float* C; };

// ---------------------------------------------------------------------------
// mma.sync bf16 split-3 GEMM: C[m][n] = sum_k A[m,k]*W[n,k] + bias[n]
// 128x128 tile, 8 warps (64x32 each), K-chunk 32.
// headmode=1: scatter to [b*H+h][s][e]; headmode=0: row-major [M,ND].
// ---------------------------------------------------------------------------
#define KC2 32
#define NCHUNK2 (ND / KC2)   // 32
#define SSTR 20              // uint32 words per 32-half row (80B, conflict-free frag loads)

#define MMA16816(c, a, b) \
  asm volatile("mma.sync.aligned.m16n8k16.row.col.f32.bf16.bf16.f32 " \
    "{%0,%1,%2,%3}, {%4,%5,%6,%7}, {%8,%9}, {%0,%1,%2,%3};" \
    : "+f"((c)[0]), "+f"((c)[1]), "+f"((c)[2]), "+f"((c)[3]) \
    : "r"((a)[0]), "r"((a)[1]), "r"((a)[2]), "r"((a)[3]), \
      "r"((b)[0]), "r"((b)[1]))

__device__ __forceinline__ void cvt_pair(float x, float y, uint32_t& hi, uint32_t& lo) {
    __nv_bfloat162 h = __floats2bfloat162_rn(x, y);     // low=x, high=y
    float hx = __bfloat162float(__low2bfloat16(h));
    float hy = __bfloat162float(__high2bfloat16(h));
    __nv_bfloat162 l = __floats2bfloat162_rn(x - hx, y - hy);
    hi = *reinterpret_cast<uint32_t*>(&h);
    lo = *reinterpret_cast<uint32_t*>(&l);
}

__global__ __launch_bounds__(256, 1) void gemm_mma(GArgs a0, GArgs a1, GArgs a2, int headmode)
{
    GArgs g = (blockIdx.z == 0) ? a0 : (blockIdx.z == 1) ? a1 : a2;
    __shared__ uint32_t sm32[4 * 128 * SSTR];   // Ahi, Alo, Bhi, Blo  (40960 B)
    uint32_t* sAh = sm32;
    uint32_t* sAl = sm32 + 128 * SSTR;
    uint32_t* sBh = sm32 + 2 * 128 * SSTR;
    uint32_t* sBl = sm32 + 3 * 128 * SSTR;

    const int tid = threadIdx.x;
    const int warp = tid >> 5;
    const int lane = tid & 31;
    const int r4 = lane >> 2, q4 = lane & 3;
    const int m0w = (warp >> 2) * 64;     // warp row base (0/64)
    const int n0w = (warp & 3) * 32;      // warp col base (0/32/64/96)

    const int mBase = blockIdx.y * 128;
    const int nBase = blockIdx.x * 128;
    const float* Ap = g.A + (size_t)mBase * ND;
    const float* Wp = g.W + (size_t)nBase * ND;

    float acc[4][4][4];
#pragma unroll
    for (int mf = 0; mf < 4; mf++)
#pragma unroll
        for (int nf = 0; nf < 4; nf++)
#pragma unroll
            for (int c = 0; c < 4; c++) acc[mf][nf][c] = 0.f;

    // staging regs for one chunk (8 float4 = 32 floats per thread)
    float4 st[8];
    // per-thread source mapping
    int rowT[8], f4T[8], selT[8];
#pragma unroll
    for (int it = 0; it < 8; it++) {
        int gidx = tid + it * 256;
        selT[it] = gidx >> 10;
        int gg = gidx & 1023;
        rowT[it] = gg >> 3;
        f4T[it] = gg & 7;
    }

    // preload chunk 0
#pragma unroll
    for (int it = 0; it < 8; it++) {
        const float* src = (selT[it] ? Wp : Ap) + (size_t)rowT[it] * ND + f4T[it] * 4;
        st[it] = *(const float4*)src;
    }

    for (int ch = 0; ch < NCHUNK2; ch++) {
        __syncthreads();   // previous compute done before overwrite
#pragma unroll
        for (int it = 0; it < 8; it++) {
            uint32_t h0, l0, h1, l1;
            cvt_pair(st[it].x, st[it].y, h0, l0);
            cvt_pair(st[it].z, st[it].w, h1, l1);
            uint32_t* dh = selT[it] ? sBh : sAh;
            uint32_t* dl = selT[it] ? sBl : sAl;
            int off = rowT[it] * SSTR + f4T[it] * 2;
            dh[off] = h0; dh[off + 1] = h1;
            dl[off] = l0; dl[off + 1] = l1;
        }
        __syncthreads();

        if (ch + 1 < NCHUNK2) {
            int k0n = (ch + 1) * KC2;
#pragma unroll
            for (int it = 0; it < 8; it++) {
                const float* src = (selT[it] ? Wp : Ap) + (size_t)rowT[it] * ND + k0n + f4T[it] * 4;
                st[it] = *(const float4*)src;
            }
        }

#pragma unroll
        for (int ks = 0; ks < 2; ks++) {
            const int kw = ks * 8;
            uint32_t bh[4][2], bl[4][2];
#pragma unroll
            for (int nf = 0; nf < 4; nf++) {
                int off = (n0w + nf * 8 + r4) * SSTR + kw + q4;
                bh[nf][0] = sBh[off]; bh[nf][1] = sBh[off + 4];
                bl[nf][0] = sBl[off]; bl[nf][1] = sBl[off + 4];
            }
#pragma unroll
            for (int mf = 0; mf < 4; mf++) {
                int off = (m0w + mf * 16 + r4) * SSTR + kw + q4;
                uint32_t ah[4], al[4];
                ah[0] = sAh[off];             ah[1] = sAh[off + 8 * SSTR];
                ah[2] = sAh[off + 4];         ah[3] = sAh[off + 8 * SSTR + 4];
                al[0] = sAl[off];             al[1] = sAl[off + 8 * SSTR];
                al[2] = sAl[off + 4];         al[3] = sAl[off + 8 * SSTR + 4];
#pragma unroll
                for (int nf = 0; nf < 4; nf++) {
                    MMA16816(acc[mf][nf], ah, bh[nf]);
                    MMA16816(acc[mf][nf], ah, bl[nf]);
                    MMA16816(acc[mf][nf], al, bh[nf]);
                }
            }
        }
    }

    // Epilogue: fragment (mf,nf): rows m0w+mf*16+r4 (+8), cols n0w+nf*8+2*q4 (+1)
#pragma unroll
    for (int nf = 0; nf < 4; nf++) {
        const int n = nBase + n0w + nf * 8 + q4 * 2;
        const float b0 = __ldg(g.bias + n);
        const float b1 = __ldg(g.bias + n + 1);
#pragma unroll
        for (int mf = 0; mf < 4; mf++) {
#pragma unroll
            for (int half = 0; half < 2; half++) {
                const int m = mBase + m0w + mf * 16 + r4 + half * 8;
                float2 val = make_float2(acc[mf][nf][half * 2] + b0,
                                         acc[mf][nf][half * 2 + 1] + b1);
                float* dst;
                if (headmode) {
                    int b = m >> 11, s = m & (NS - 1);
                    int h = n >> 6, e = n & 63;
                    dst = g.C + ((size_t)((b * NH + h) * NS + s)) * HDIM + e;
                } else {
                    dst = g.C + (size_t)m * ND + n;
                }
                *(float2*)dst = val;
            }
        }
    }
}

// ---------------------------------------------------------------------------
// Flash attention: BQ=64, BKV=64, hd=64, 128 threads (unchanged, proven)
// ---------------------------------------------------------------------------
__global__ __launch_bounds__(128) void attn_k(const float* __restrict__ gq,
                                              const float* __restrict__ gk,
                                              const float* __restrict__ gv,
                                              const int* __restrict__ mask,
                                              float* __restrict__ ctx)
{
    extern __shared__ float sm[];
    float* Qs  = sm;               // [64][65]
    float* KPs = sm + 64 * 65;     // [64][65]  (K tile, then reused for P)
    float* Vs  = sm + 2 * 64 * 65; // [64][64]
    __shared__ int maskS[64];

    int tid = threadIdx.x;
    int ty = tid >> 3, tx = tid & 7;
    int qt = blockIdx.x;
    int bh = blockIdx.y;
    int b = bh >> 4;
    int h = bh & 15;

    size_t headoff = (size_t)bh * NS * HDIM;

    {
        const float* qp = gq + headoff + (size_t)qt * 64 * HDIM;
        for (int i = tid; i < 64 * 16; i += 128) {
            int r = i >> 4, e4 = (i & 15) << 2;
            float4 v = *(const float4*)(qp + r * HDIM + e4);
            float* d = Qs + r * 65 + e4;
            d[0] = v.x * 0.125f; d[1] = v.y * 0.125f; d[2] = v.z * 0.125f; d[3] = v.w * 0.125f;
        }
    }

    float mI[4], lI[4], O[4][8];
#pragma unroll
    for (int i = 0; i < 4; i++) {
        mI[i] = -INFINITY; lI[i] = 0.f;
#pragma unroll
        for (int j = 0; j < 8; j++) O[i][j] = 0.f;
    }

    const int* mrow = mask + (size_t)b * NS;

    for (int kt = 0; kt < NS / 64; kt++) {
        __syncthreads();
        const float* kp = gk + headoff + (size_t)kt * 64 * HDIM;
        const float* vp = gv + headoff + (size_t)kt * 64 * HDIM;
        for (int i = tid; i < 1024; i += 128) {
            int r = i >> 4, e4 = (i & 15) << 2;
            float4 kv = *(const float4*)(kp + r * HDIM + e4);
            float* kd = KPs + r * 65 + e4;
            kd[0] = kv.x; kd[1] = kv.y; kd[2] = kv.z; kd[3] = kv.w;
            float4 vv = *(const float4*)(vp + r * HDIM + e4);
            *(float4*)(Vs + r * 64 + e4) = vv;
        }
        if (tid < 64) maskS[tid] = mrow[kt * 64 + tid];
        __syncthreads();

        float s[4][8];
#pragma unroll
        for (int i = 0; i < 4; i++)
#pragma unroll
            for (int j = 0; j < 8; j++) s[i][j] = 0.f;

        for (int e = 0; e < 64; e++) {
            float qf[4], kf[8];
#pragma unroll
            for (int i = 0; i < 4; i++) qf[i] = Qs[(4 * ty + i) * 65 + e];
#pragma unroll
            for (int j = 0; j < 8; j++) kf[j] = KPs[(8 * tx + j) * 65 + e];
#pragma unroll
            for (int i = 0; i < 4; i++)
#pragma unroll
                for (int j = 0; j < 8; j++)
                    s[i][j] = fmaf(qf[i], kf[j], s[i][j]);
        }

#pragma unroll
        for (int j = 0; j < 8; j++) {
            if (maskS[8 * tx + j]) {
#pragma unroll
                for (int i = 0; i < 4; i++) s[i][j] = -9e9f;
            }
        }

#pragma unroll
        for (int i = 0; i < 4; i++) {
            float mt = s[i][0];
#pragma unroll
            for (int j = 1; j < 8; j++) mt = fmaxf(mt, s[i][j]);
            mt = fmaxf(mt, __shfl_xor_sync(0xffffffffu, mt, 1));
            mt = fmaxf(mt, __shfl_xor_sync(0xffffffffu, mt, 2));
            mt = fmaxf(mt, __shfl_xor_sync(0xffffffffu, mt, 4));
            float mNew = fmaxf(mI[i], mt);
            float f = __expf(mI[i] - mNew);
            float rs = 0.f;
#pragma unroll
            for (int j = 0; j < 8; j++) { s[i][j] = __expf(s[i][j] - mNew); rs += s[i][j]; }
            rs += __shfl_xor_sync(0xffffffffu, rs, 1);
            rs += __shfl_xor_sync(0xffffffffu, rs, 2);
            rs += __shfl_xor_sync(0xffffffffu, rs, 4);
            lI[i] = lI[i] * f + rs;
#pragma unroll
            for (int j = 0; j < 8; j++) O[i][j] *= f;
            mI[i] = mNew;
        }

        __syncthreads();
#pragma unroll
        for (int i = 0; i < 4; i++)
#pragma unroll
            for (int j = 0; j < 8; j++)
                KPs[(4 * ty + i) * 65 + 8 * tx + j] = s[i][j];
        __syncthreads();

        for (int k = 0; k < 64; k++) {
            float pf[4], vf[8];
#pragma unroll
            for (int i = 0; i < 4; i++) pf[i] = KPs[(4 * ty + i) * 65 + k];
#pragma unroll
            for (int j = 0; j < 8; j++) vf[j] = Vs[k * 64 + 8 * tx + j];
#pragma unroll
            for (int i = 0; i < 4; i++)
#pragma unroll
                for (int j = 0; j < 8; j++)
                    O[i][j] = fmaf(pf[i], vf[j], O[i][j]);
        }
    }

#pragma unroll
    for (int i = 0; i < 4; i++) {
        float inv = 1.f / lI[i];
        int srow = qt * 64 + 4 * ty + i;
        float* op = ctx + ((size_t)(b * NS + srow)) * ND + h * HDIM + 8 * tx;
        float4 r0 = make_float4(O[i][0] * inv, O[i][1] * inv, O[i][2] * inv, O[i][3] * inv);
        float4 r1 = make_float4(O[i][4] * inv, O[i][5] * inv, O[i][6] * inv, O[i][7] * inv);
        *(float4*)op = r0;
        *(float4*)(op + 4) = r1;
    }
}

extern "C" void kernel_launch(void* const* d_in, const int* in_sizes, int n_in,
                              void* d_out, int out_size)
{
    const float* q  = (const float*)d_in[0];
    const float* k  = (const float*)d_in[1];
    const float* v  = (const float*)d_in[2];
    const int* mask = (const int*)d_in[3];
    const float* Wq = (const float*)d_in[4];
    const float* bq = (const float*)d_in[5];
    const float* Wk = (const float*)d_in[6];
    const float* bk = (const float*)d_in[7];
    const float* Wv = (const float*)d_in[8];
    const float* bv = (const float*)d_in[9];
    const float* Wo = (const float*)d_in[10];
    const float* bo = (const float*)d_in[11];
    float* out = (float*)d_out;

    float *gq_d, *gk_d, *gv_d, *gctx_d;
    cudaGetSymbolAddress((void**)&gq_d, g_q);
    cudaGetSymbolAddress((void**)&gk_d, g_k);
    cudaGetSymbolAddress((void**)&gv_d, g_v);
    cudaGetSymbolAddress((void**)&gctx_d, g_ctx);

    const int smem_attn = (2 * 64 * 65 + 64 * 64) * (int)sizeof(float);  // 49664
    cudaFuncSetAttribute(attn_k, cudaFuncAttributeMaxDynamicSharedMemorySize, smem_attn);

    // QKV projections (z-fused, tensor cores via mma.sync)
    GArgs aq{q, Wq, bq, gq_d};
    GArgs ak{k, Wk, bk, gk_d};
    GArgs av{v, Wv, bv, gv_d};
    gemm_mma<<<dim3(ND / 128, MROWS / 128, 3), 256>>>(aq, ak, av, 1);

    // attention
    attn_k<<<dim3(NS / 64, NB * NH), 128, smem_attn>>>(gq_d, gk_d, gv_d, mask, gctx_d);

    // output projection
    GArgs ao{gctx_d, Wo, bo, out};
    gemm_mma<<<dim3(ND / 128, MROWS / 128, 1), 256>>>(ao, ao, ao, 0);
}

// round 6
// speedup vs baseline: 3.1158x; 2.3165x over previous
#include <cuda_runtime.h>
#include <cuda_bf16.h>
#include <math.h>
#include <stdint.h>

#define NB 2
#define NS 2048
#define ND 1024
#define NH 16
#define HDIM 64
#define MROWS (NB*NS)

// Scratch (device globals; no allocations allowed)
__device__ float g_q[NB*NH*NS*HDIM];    // [b*H+h][s][e]
__device__ float g_k[NB*NH*NS*HDIM];
__device__ float g_v[NB*NH*NS*HDIM];
__device__ float g_ctx[NB*NS*ND];       // [b][s][h*64+e]

struct GArgs { const float* A; const float* W; const float* bias; float* C; };

#define MMA16816(c, a, b) \
  asm volatile("mma.sync.aligned.m16n8k16.row.col.f32.bf16.bf16.f32 " \
    "{%0,%1,%2,%3}, {%4,%5,%6,%7}, {%8,%9}, {%0,%1,%2,%3};" \
    : "+f"((c)[0]), "+f"((c)[1]), "+f"((c)[2]), "+f"((c)[3]) \
    : "r"((a)[0]), "r"((a)[1]), "r"((a)[2]), "r"((a)[3]), \
      "r"((b)[0]), "r"((b)[1]))

__device__ __forceinline__ void cvt_pair(float x, float y, uint32_t& hi, uint32_t& lo) {
    __nv_bfloat162 h = __floats2bfloat162_rn(x, y);     // low=x, high=y
    float hx = __bfloat162float(__low2bfloat16(h));
    float hy = __bfloat162float(__high2bfloat16(h));
    __nv_bfloat162 l = __floats2bfloat162_rn(x - hx, y - hy);
    hi = *reinterpret_cast<uint32_t*>(&h);
    lo = *reinterpret_cast<uint32_t*>(&l);
}
__device__ __forceinline__ float ex2f(float x) {
    float y; asm("ex2.approx.ftz.f32 %0, %1;" : "=f"(y) : "f"(x)); return y;
}
__device__ __forceinline__ uint32_t smem_u32(const void* p) {
    uint32_t a;
    asm("{ .reg .u64 t; cvta.to.shared.u64 t, %1; cvt.u32.u64 %0, t; }" : "=r"(a) : "l"(p));
    return a;
}
__device__ __forceinline__ void ldsm_x4_t(uint32_t& r0, uint32_t& r1, uint32_t& r2, uint32_t& r3,
                                          uint32_t a) {
    asm volatile("ldmatrix.sync.aligned.m8n8.x4.trans.shared.b16 {%0,%1,%2,%3}, [%4];"
                 : "=r"(r0), "=r"(r1), "=r"(r2), "=r"(r3) : "r"(a));
}

// ---------------------------------------------------------------------------
// mma.sync bf16 split-3 GEMM (unchanged from R4, proven)
// ---------------------------------------------------------------------------
#define KC2 32
#define NCHUNK2 (ND / KC2)
#define SSTR 20

__global__ __launch_bounds__(256, 1) void gemm_mma(GArgs a0, GArgs a1, GArgs a2, int headmode)
{
    GArgs g = (blockIdx.z == 0) ? a0 : (blockIdx.z == 1) ? a1 : a2;
    __shared__ uint32_t sm32[4 * 128 * SSTR];
    uint32_t* sAh = sm32;
    uint32_t* sAl = sm32 + 128 * SSTR;
    uint32_t* sBh = sm32 + 2 * 128 * SSTR;
    uint32_t* sBl = sm32 + 3 * 128 * SSTR;

    const int tid = threadIdx.x;
    const int warp = tid >> 5;
    const int lane = tid & 31;
    const int r4 = lane >> 2, q4 = lane & 3;
    const int m0w = (warp >> 2) * 64;
    const int n0w = (warp & 3) * 32;

    const int mBase = blockIdx.y * 128;
    const int nBase = blockIdx.x * 128;
    const float* Ap = g.A + (size_t)mBase * ND;
    const float* Wp = g.W + (size_t)nBase * ND;

    float acc[4][4][4];
#pragma unroll
    for (int mf = 0; mf < 4; mf++)
#pragma unroll
        for (int nf = 0; nf < 4; nf++)
#pragma unroll
            for (int c = 0; c < 4; c++) acc[mf][nf][c] = 0.f;

    float4 st[8];
    int rowT[8], f4T[8], selT[8];
#pragma unroll
    for (int it = 0; it < 8; it++) {
        int gidx = tid + it * 256;
        selT[it] = gidx >> 10;
        int gg = gidx & 1023;
        rowT[it] = gg >> 3;
        f4T[it] = gg & 7;
    }
#pragma unroll
    for (int it = 0; it < 8; it++) {
        const float* src = (selT[it] ? Wp : Ap) + (size_t)rowT[it] * ND + f4T[it] * 4;
        st[it] = *(const float4*)src;
    }

    for (int ch = 0; ch < NCHUNK2; ch++) {
        __syncthreads();
#pragma unroll
        for (int it = 0; it < 8; it++) {
            uint32_t h0, l0, h1, l1;
            cvt_pair(st[it].x, st[it].y, h0, l0);
            cvt_pair(st[it].z, st[it].w, h1, l1);
            uint32_t* dh = selT[it] ? sBh : sAh;
            uint32_t* dl = selT[it] ? sBl : sAl;
            int off = rowT[it] * SSTR + f4T[it] * 2;
            dh[off] = h0; dh[off + 1] = h1;
            dl[off] = l0; dl[off + 1] = l1;
        }
        __syncthreads();

        if (ch + 1 < NCHUNK2) {
            int k0n = (ch + 1) * KC2;
#pragma unroll
            for (int it = 0; it < 8; it++) {
                const float* src = (selT[it] ? Wp : Ap) + (size_t)rowT[it] * ND + k0n + f4T[it] * 4;
                st[it] = *(const float4*)src;
            }
        }

#pragma unroll
        for (int ks = 0; ks < 2; ks++) {
            const int kw = ks * 8;
            uint32_t bh[4][2], bl[4][2];
#pragma unroll
            for (int nf = 0; nf < 4; nf++) {
                int off = (n0w + nf * 8 + r4) * SSTR + kw + q4;
                bh[nf][0] = sBh[off]; bh[nf][1] = sBh[off + 4];
                bl[nf][0] = sBl[off]; bl[nf][1] = sBl[off + 4];
            }
#pragma unroll
            for (int mf = 0; mf < 4; mf++) {
                int off = (m0w + mf * 16 + r4) * SSTR + kw + q4;
                uint32_t ah[4], al[4];
                ah[0] = sAh[off];             ah[1] = sAh[off + 8 * SSTR];
                ah[2] = sAh[off + 4];         ah[3] = sAh[off + 8 * SSTR + 4];
                al[0] = sAl[off];             al[1] = sAl[off + 8 * SSTR];
                al[2] = sAl[off + 4];         al[3] = sAl[off + 8 * SSTR + 4];
#pragma unroll
                for (int nf = 0; nf < 4; nf++) {
                    MMA16816(acc[mf][nf], ah, bh[nf]);
                    MMA16816(acc[mf][nf], ah, bl[nf]);
                    MMA16816(acc[mf][nf], al, bh[nf]);
                }
            }
        }
    }

#pragma unroll
    for (int nf = 0; nf < 4; nf++) {
        const int n = nBase + n0w + nf * 8 + q4 * 2;
        const float b0 = __ldg(g.bias + n);
        const float b1 = __ldg(g.bias + n + 1);
#pragma unroll
        for (int mf = 0; mf < 4; mf++) {
#pragma unroll
            for (int half = 0; half < 2; half++) {
                const int m = mBase + m0w + mf * 16 + r4 + half * 8;
                float2 val = make_float2(acc[mf][nf][half * 2] + b0,
                                         acc[mf][nf][half * 2 + 1] + b1);
                float* dst;
                if (headmode) {
                    int b = m >> 11, s = m & (NS - 1);
                    int h = n >> 6, e = n & 63;
                    dst = g.C + ((size_t)((b * NH + h) * NS + s)) * HDIM + e;
                } else {
                    dst = g.C + (size_t)m * ND + n;
                }
                *(float2*)dst = val;
            }
        }
    }
}

// ---------------------------------------------------------------------------
// Tensor-core flash attention, split-3 on BOTH QK^T and PV.
// BQ=128 (8 warps x 16 rows), BKV=64, hd=64.
// Q prescaled by 0.125*log2(e); softmax in exp2 domain (equivalent).
// smem (u32 words): phase1: Qhi[128*36], Qlo[128*36]
//   phase2: Khi[64*36] Klo[64*36] Vhi[64*36] Vlo[64*36] mask[64]
// ---------------------------------------------------------------------------
#define KSTR 36                    // u32 words per 64-element bf16 row (144B)
#define QSCALE 0.18033688011f      // 0.125 * log2(e)

__global__ __launch_bounds__(256, 1) void attn_mma(const float* __restrict__ gq,
                                                   const float* __restrict__ gk,
                                                   const float* __restrict__ gv,
                                                   const int* __restrict__ mask,
                                                   float* __restrict__ ctx)
{
    extern __shared__ uint32_t dynsm[];
    uint32_t* sKh = dynsm;                 // 64*36
    uint32_t* sKl = dynsm + 64 * KSTR;
    uint32_t* sVh = dynsm + 2 * 64 * KSTR;
    uint32_t* sVl = dynsm + 3 * 64 * KSTR;
    int*      sMk = (int*)(dynsm + 4 * 64 * KSTR);  // 64 ints
    uint32_t* sQh = dynsm;                 // phase 1 only: 128*36
    uint32_t* sQl = dynsm + 128 * KSTR;

    const int tid = threadIdx.x;
    const int warp = tid >> 5;
    const int lane = tid & 31;
    const int r4 = lane >> 2, q4 = lane & 3;
    const int qt = blockIdx.x;     // 0..15
    const int bh = blockIdx.y;     // 0..31
    const int b = bh >> 4, h = bh & 15;
    const size_t headoff = (size_t)bh * NS * HDIM;

    // ---- Phase 1: stage Q tile (scaled) to smem as bf16 hi/lo, load A-frags ----
    {
        const float* qp = gq + headoff + (size_t)qt * 128 * HDIM;
#pragma unroll
        for (int it = 0; it < 8; it++) {
            int g = tid + it * 256;
            int row = g >> 4, e0 = (g & 15) * 4;
            float4 v = *(const float4*)(qp + row * HDIM + e0);
            uint32_t h0, l0, h1, l1;
            cvt_pair(v.x * QSCALE, v.y * QSCALE, h0, l0);
            cvt_pair(v.z * QSCALE, v.w * QSCALE, h1, l1);
            int off = row * KSTR + (g & 15) * 2;
            sQh[off] = h0; sQh[off + 1] = h1;
            sQl[off] = l0; sQl[off + 1] = l1;
        }
    }
    __syncthreads();

    uint32_t Qh[4][4], Ql[4][4];
#pragma unroll
    for (int kf = 0; kf < 4; kf++) {
        int off = (16 * warp + r4) * KSTR + 8 * kf + q4;
        Qh[kf][0] = sQh[off];              Qh[kf][1] = sQh[off + 8 * KSTR];
        Qh[kf][2] = sQh[off + 4];          Qh[kf][3] = sQh[off + 8 * KSTR + 4];
        Ql[kf][0] = sQl[off];              Ql[kf][1] = sQl[off + 8 * KSTR];
        Ql[kf][2] = sQl[off + 4];          Ql[kf][3] = sQl[off + 8 * KSTR + 4];
    }
    __syncthreads();   // Q region now reusable as K/V

    // ldmatrix.x4 base: lanes 0-15 -> Vhi rows, lanes 16-31 -> Vlo rows
    const uint32_t vAddr =
        smem_u32(lane < 16 ? sVh : sVl) + (lane & 15) * (KSTR * 4);

    float O[8][4];
    float mI0 = -INFINITY, mI1 = -INFINITY, lI0 = 0.f, lI1 = 0.f;
#pragma unroll
    for (int nf = 0; nf < 8; nf++)
#pragma unroll
        for (int c = 0; c < 4; c++) O[nf][c] = 0.f;

    const float* kbase = gk + headoff;
    const float* vbase = gv + headoff;
    const int* mrow = mask + (size_t)b * NS;

    float4 stK[4], stV[4];
    int mkld = 0;
#pragma unroll
    for (int it = 0; it < 4; it++) {
        int g = tid + it * 256;
        int s = g >> 4, e0 = (g & 15) * 4;
        stK[it] = *(const float4*)(kbase + s * HDIM + e0);
        stV[it] = *(const float4*)(vbase + s * HDIM + e0);
    }
    if (tid < 64) mkld = mrow[tid];

    for (int kt = 0; kt < NS / 64; kt++) {
        __syncthreads();   // previous tile's smem reads complete
#pragma unroll
        for (int it = 0; it < 4; it++) {
            int g = tid + it * 256;
            int s = g >> 4;
            int w2 = (g & 15) * 2;
            int off = s * KSTR + w2;
            uint32_t h0, l0, h1, l1;
            cvt_pair(stK[it].x, stK[it].y, h0, l0);
            cvt_pair(stK[it].z, stK[it].w, h1, l1);
            sKh[off] = h0; sKh[off + 1] = h1;
            sKl[off] = l0; sKl[off + 1] = l1;
            cvt_pair(stV[it].x, stV[it].y, h0, l0);
            cvt_pair(stV[it].z, stV[it].w, h1, l1);
            sVh[off] = h0; sVh[off + 1] = h1;
            sVl[off] = l0; sVl[off + 1] = l1;
        }
        if (tid < 64) sMk[tid] = mkld;
        __syncthreads();

        // prefetch next tile
        if (kt + 1 < NS / 64) {
            const float* kp = kbase + (size_t)(kt + 1) * 64 * HDIM;
            const float* vp = vbase + (size_t)(kt + 1) * 64 * HDIM;
#pragma unroll
            for (int it = 0; it < 4; it++) {
                int g = tid + it * 256;
                int s = g >> 4, e0 = (g & 15) * 4;
                stK[it] = *(const float4*)(kp + s * HDIM + e0);
                stV[it] = *(const float4*)(vp + s * HDIM + e0);
            }
            if (tid < 64) mkld = mrow[(kt + 1) * 64 + tid];
        }

        // ---- S = Q K^T (split-3) ----
        float S[8][4];
#pragma unroll
        for (int nf = 0; nf < 8; nf++)
#pragma unroll
            for (int c = 0; c < 4; c++) S[nf][c] = 0.f;

#pragma unroll
        for (int kf = 0; kf < 4; kf++) {
#pragma unroll
            for (int nf = 0; nf < 8; nf++) {
                int off = (8 * nf + r4) * KSTR + 8 * kf + q4;
                uint32_t bhh[2], bll[2];
                bhh[0] = sKh[off]; bhh[1] = sKh[off + 4];
                bll[0] = sKl[off]; bll[1] = sKl[off + 4];
                MMA16816(S[nf], Qh[kf], bhh);
                MMA16816(S[nf], Qh[kf], bll);
                MMA16816(S[nf], Ql[kf], bhh);
            }
        }

        // ---- mask + online softmax (exp2 domain) ----
        float mt0 = -INFINITY, mt1 = -INFINITY;
#pragma unroll
        for (int nf = 0; nf < 8; nf++) {
            int c0 = 8 * nf + 2 * q4;
            if (sMk[c0])     { S[nf][0] = -9e9f; S[nf][2] = -9e9f; }
            if (sMk[c0 + 1]) { S[nf][1] = -9e9f; S[nf][3] = -9e9f; }
            mt0 = fmaxf(mt0, fmaxf(S[nf][0], S[nf][1]));
            mt1 = fmaxf(mt1, fmaxf(S[nf][2], S[nf][3]));
        }
        mt0 = fmaxf(mt0, __shfl_xor_sync(0xffffffffu, mt0, 1));
        mt0 = fmaxf(mt0, __shfl_xor_sync(0xffffffffu, mt0, 2));
        mt1 = fmaxf(mt1, __shfl_xor_sync(0xffffffffu, mt1, 1));
        mt1 = fmaxf(mt1, __shfl_xor_sync(0xffffffffu, mt1, 2));

        float mN0 = fmaxf(mI0, mt0), mN1 = fmaxf(mI1, mt1);
        float f0 = ex2f(mI0 - mN0), f1 = ex2f(mI1 - mN1);
        float rs0 = 0.f, rs1 = 0.f;
#pragma unroll
        for (int nf = 0; nf < 8; nf++) {
            S[nf][0] = ex2f(S[nf][0] - mN0);
            S[nf][1] = ex2f(S[nf][1] - mN0);
            S[nf][2] = ex2f(S[nf][2] - mN1);
            S[nf][3] = ex2f(S[nf][3] - mN1);
            rs0 += S[nf][0] + S[nf][1];
            rs1 += S[nf][2] + S[nf][3];
        }
        rs0 += __shfl_xor_sync(0xffffffffu, rs0, 1);
        rs0 += __shfl_xor_sync(0xffffffffu, rs0, 2);
        rs1 += __shfl_xor_sync(0xffffffffu, rs1, 1);
        rs1 += __shfl_xor_sync(0xffffffffu, rs1, 2);
        lI0 = lI0 * f0 + rs0;
        lI1 = lI1 * f1 + rs1;
        mI0 = mN0; mI1 = mN1;
#pragma unroll
        for (int nf = 0; nf < 8; nf++) {
            O[nf][0] *= f0; O[nf][1] *= f0;
            O[nf][2] *= f1; O[nf][3] *= f1;
        }

        // ---- repack P into split hi/lo A-frags (registers only) ----
        uint32_t Ph[4][4], Pl[4][4];
#pragma unroll
        for (int kf = 0; kf < 4; kf++) {
            cvt_pair(S[2*kf][0],     S[2*kf][1],     Ph[kf][0], Pl[kf][0]);
            cvt_pair(S[2*kf][2],     S[2*kf][3],     Ph[kf][1], Pl[kf][1]);
            cvt_pair(S[2*kf + 1][0], S[2*kf + 1][1], Ph[kf][2], Pl[kf][2]);
            cvt_pair(S[2*kf + 1][2], S[2*kf + 1][3], Ph[kf][3], Pl[kf][3]);
        }

        // ---- O += P V  (split-3; Vhi/Vlo frags in one ldmatrix.x4) ----
#pragma unroll
        for (int kf = 0; kf < 4; kf++) {
            uint32_t abase = vAddr + kf * 16 * (KSTR * 4);
#pragma unroll
            for (int nf = 0; nf < 8; nf++) {
                uint32_t vh[2], vl[2];
                ldsm_x4_t(vh[0], vh[1], vl[0], vl[1], abase + nf * 16);
                MMA16816(O[nf], Ph[kf], vh);
                MMA16816(O[nf], Ph[kf], vl);
                MMA16816(O[nf], Pl[kf], vh);
            }
        }
    }

    // ---- normalize + write ctx [b][s][h*64+e] ----
    const float inv0 = 1.f / lI0;
    const float inv1 = 1.f / lI1;
    const int row0 = qt * 128 + 16 * warp + r4;
    float* op0 = ctx + ((size_t)(b * NS + row0)) * ND + h * HDIM + 2 * q4;
    float* op1 = ctx + ((size_t)(b * NS + row0 + 8)) * ND + h * HDIM + 2 * q4;
#pragma unroll
    for (int nf = 0; nf < 8; nf++) {
        *(float2*)(op0 + 8 * nf) = make_float2(O[nf][0] * inv0, O[nf][1] * inv0);
        *(float2*)(op1 + 8 * nf) = make_float2(O[nf][2] * inv1, O[nf][3] * inv1);
    }
}

extern "C" void kernel_launch(void* const* d_in, const int* in_sizes, int n_in,
                              void* d_out, int out_size)
{
    const float* q  = (const float*)d_in[0];
    const float* k  = (const float*)d_in[1];
    const float* v  = (const float*)d_in[2];
    const int* mask = (const int*)d_in[3];
    const float* Wq = (const float*)d_in[4];
    const float* bq = (const float*)d_in[5];
    const float* Wk = (const float*)d_in[6];
    const float* bk = (const float*)d_in[7];
    const float* Wv = (const float*)d_in[8];
    const float* bv = (const float*)d_in[9];
    const float* Wo = (const float*)d_in[10];
    const float* bo = (const float*)d_in[11];
    float* out = (float*)d_out;

    float *gq_d, *gk_d, *gv_d, *gctx_d;
    cudaGetSymbolAddress((void**)&gq_d, g_q);
    cudaGetSymbolAddress((void**)&gk_d, g_k);
    cudaGetSymbolAddress((void**)&gv_d, g_v);
    cudaGetSymbolAddress((void**)&gctx_d, g_ctx);

    const int smem_attn = (4 * 64 * KSTR + 64) * 4;   // 37120 B (phase1 Q fits: 36864)
    cudaFuncSetAttribute(attn_mma, cudaFuncAttributeMaxDynamicSharedMemorySize, smem_attn);

    // QKV projections (z-fused, mma.sync)
    GArgs aq{q, Wq, bq, gq_d};
    GArgs ak{k, Wk, bk, gk_d};
    GArgs av{v, Wv, bv, gv_d};
    gemm_mma<<<dim3(ND / 128, MROWS / 128, 3), 256>>>(aq, ak, av, 1);

    // attention (tensor cores, split-3 everywhere)
    attn_mma<<<dim3(NS / 128, NB * NH), 256, smem_attn>>>(gq_d, gk_d, gv_d, mask, gctx_d);

    // output projection
    GArgs ao{gctx_d, Wo, bo, out};
    gemm_mma<<<dim3(ND / 128, MROWS / 128, 1), 256>>>(ao, ao, ao, 0);
}

// round 7
// speedup vs baseline: 3.1169x; 1.0003x over previous
#include <cuda_runtime.h>
#include <cuda_bf16.h>
#include <math.h>
#include <stdint.h>

#define NB 2
#define NS 2048
#define ND 1024
#define NH 16
#define HDIM 64
#define MROWS (NB*NS)

// Scratch (device globals; no allocations allowed)
__device__ float g_ctx[NB*NS*ND];              // [b][s][h*64+e]
// bf16 hi/lo planes, head layout [b*H+h][s][e], 2 bf16 per u32 word
__device__ uint32_t g_qh[NB*NH*NS*HDIM/2];
__device__ uint32_t g_ql[NB*NH*NS*HDIM/2];
__device__ uint32_t g_kh[NB*NH*NS*HDIM/2];
__device__ uint32_t g_kl[NB*NH*NS*HDIM/2];
__device__ uint32_t g_vh[NB*NH*NS*HDIM/2];
__device__ uint32_t g_vl[NB*NH*NS*HDIM/2];

struct GArgs {
    const float* A; const float* W; const float* bias;
    float* C;                 // mode 0 fp32 out
    uint32_t* Ph; uint32_t* Pl;   // headmode bf16 planes
    float scale;
};

#define MMA16816(c, a, b) \
  asm volatile("mma.sync.aligned.m16n8k16.row.col.f32.bf16.bf16.f32 " \
    "{%0,%1,%2,%3}, {%4,%5,%6,%7}, {%8,%9}, {%0,%1,%2,%3};" \
    : "+f"((c)[0]), "+f"((c)[1]), "+f"((c)[2]), "+f"((c)[3]) \
    : "r"((a)[0]), "r"((a)[1]), "r"((a)[2]), "r"((a)[3]), \
      "r"((b)[0]), "r"((b)[1]))

__device__ __forceinline__ void cvt_pair(float x, float y, uint32_t& hi, uint32_t& lo) {
    __nv_bfloat162 h = __floats2bfloat162_rn(x, y);     // low=x, high=y
    float hx = __bfloat162float(__low2bfloat16(h));
    float hy = __bfloat162float(__high2bfloat16(h));
    __nv_bfloat162 l = __floats2bfloat162_rn(x - hx, y - hy);
    hi = *reinterpret_cast<uint32_t*>(&h);
    lo = *reinterpret_cast<uint32_t*>(&l);
}
__device__ __forceinline__ float ex2f(float x) {
    float y; asm("ex2.approx.ftz.f32 %0, %1;" : "=f"(y) : "f"(x)); return y;
}
__device__ __forceinline__ uint32_t smem_u32(const void* p) {
    uint32_t a;
    asm("{ .reg .u64 t; cvta.to.shared.u64 t, %1; cvt.u32.u64 %0, t; }" : "=r"(a) : "l"(p));
    return a;
}
__device__ __forceinline__ void ldsm_x4(uint32_t& r0, uint32_t& r1, uint32_t& r2, uint32_t& r3,
                                        uint32_t a) {
    asm volatile("ldmatrix.sync.aligned.m8n8.x4.shared.b16 {%0,%1,%2,%3}, [%4];"
                 : "=r"(r0), "=r"(r1), "=r"(r2), "=r"(r3) : "r"(a));
}
__device__ __forceinline__ void ldsm_x4_t(uint32_t& r0, uint32_t& r1, uint32_t& r2, uint32_t& r3,
                                          uint32_t a) {
    asm volatile("ldmatrix.sync.aligned.m8n8.x4.trans.shared.b16 {%0,%1,%2,%3}, [%4];"
                 : "=r"(r0), "=r"(r1), "=r"(r2), "=r"(r3) : "r"(a));
}

#define QSCALE 0.18033688011f      // 0.125 * log2(e)

// ---------------------------------------------------------------------------
// mma.sync bf16 split-3 GEMM, double-buffered smem.
// headmode=1: write (acc+bias)*scale as bf16 hi/lo planes in head layout.
// headmode=0: write fp32 row-major (scale must be 1).
// ---------------------------------------------------------------------------
#define KC2 32
#define NCHUNK2 (ND / KC2)
#define SSTR 20
#define STAGE_W (4 * 128 * SSTR)   // u32 words per stage (10240)

__global__ __launch_bounds__(256, 1) void gemm_mma(GArgs a0, GArgs a1, GArgs a2, int headmode)
{
    GArgs g = (blockIdx.z == 0) ? a0 : (blockIdx.z == 1) ? a1 : a2;
    extern __shared__ uint32_t smg[];   // 2 stages x 40960 B

    const int tid = threadIdx.x;
    const int warp = tid >> 5;
    const int lane = tid & 31;
    const int r4 = lane >> 2, q4 = lane & 3;
    const int m0w = (warp >> 2) * 64;
    const int n0w = (warp & 3) * 32;

    const int mBase = blockIdx.y * 128;
    const int nBase = blockIdx.x * 128;
    const float* Ap = g.A + (size_t)mBase * ND;
    const float* Wp = g.W + (size_t)nBase * ND;

    float acc[4][4][4];
#pragma unroll
    for (int mf = 0; mf < 4; mf++)
#pragma unroll
        for (int nf = 0; nf < 4; nf++)
#pragma unroll
            for (int c = 0; c < 4; c++) acc[mf][nf][c] = 0.f;

    float4 st[8];
    int rowT[8], f4T[8], selT[8];
#pragma unroll
    for (int it = 0; it < 8; it++) {
        int gidx = tid + it * 256;
        selT[it] = gidx >> 10;
        int gg = gidx & 1023;
        rowT[it] = gg >> 3;
        f4T[it] = gg & 7;
    }

    // preload chunk 0, convert+store to stage 0
#pragma unroll
    for (int it = 0; it < 8; it++) {
        const float* src = (selT[it] ? Wp : Ap) + (size_t)rowT[it] * ND + f4T[it] * 4;
        st[it] = *(const float4*)src;
    }
    {
        uint32_t* sAh = smg;
        uint32_t* sAl = smg + 128 * SSTR;
        uint32_t* sBh = smg + 2 * 128 * SSTR;
        uint32_t* sBl = smg + 3 * 128 * SSTR;
#pragma unroll
        for (int it = 0; it < 8; it++) {
            uint32_t h0, l0, h1, l1;
            cvt_pair(st[it].x, st[it].y, h0, l0);
            cvt_pair(st[it].z, st[it].w, h1, l1);
            uint32_t* dh = selT[it] ? sBh : sAh;
            uint32_t* dl = selT[it] ? sBl : sAl;
            int off = rowT[it] * SSTR + f4T[it] * 2;
            dh[off] = h0; dh[off + 1] = h1;
            dl[off] = l0; dl[off + 1] = l1;
        }
    }
    __syncthreads();
    // preload chunk 1 regs
#pragma unroll
    for (int it = 0; it < 8; it++) {
        const float* src = (selT[it] ? Wp : Ap) + (size_t)rowT[it] * ND + KC2 + f4T[it] * 4;
        st[it] = *(const float4*)src;
    }

    for (int ch = 0; ch < NCHUNK2; ch++) {
        const uint32_t* S0 = smg + (ch & 1) * STAGE_W;
        const uint32_t* sAh = S0;
        const uint32_t* sAl = S0 + 128 * SSTR;
        const uint32_t* sBh = S0 + 2 * 128 * SSTR;
        const uint32_t* sBl = S0 + 3 * 128 * SSTR;

#pragma unroll
        for (int ks = 0; ks < 2; ks++) {
            const int kw = ks * 8;
            uint32_t bh[4][2], bl[4][2];
#pragma unroll
            for (int nf = 0; nf < 4; nf++) {
                int off = (n0w + nf * 8 + r4) * SSTR + kw + q4;
                bh[nf][0] = sBh[off]; bh[nf][1] = sBh[off + 4];
                bl[nf][0] = sBl[off]; bl[nf][1] = sBl[off + 4];
            }
#pragma unroll
            for (int mf = 0; mf < 4; mf++) {
                int off = (m0w + mf * 16 + r4) * SSTR + kw + q4;
                uint32_t ah[4], al[4];
                ah[0] = sAh[off];             ah[1] = sAh[off + 8 * SSTR];
                ah[2] = sAh[off + 4];         ah[3] = sAh[off + 8 * SSTR + 4];
                al[0] = sAl[off];             al[1] = sAl[off + 8 * SSTR];
                al[2] = sAl[off + 4];         al[3] = sAl[off + 8 * SSTR + 4];
#pragma unroll
                for (int nf = 0; nf < 4; nf++) {
                    MMA16816(acc[mf][nf], ah, bh[nf]);
                    MMA16816(acc[mf][nf], ah, bl[nf]);
                    MMA16816(acc[mf][nf], al, bh[nf]);
                }
            }
        }

        if (ch + 1 < NCHUNK2) {
            // convert chunk ch+1 (in regs) to the other stage
            uint32_t* D0 = smg + ((ch + 1) & 1) * STAGE_W;
            uint32_t* dAh = D0;
            uint32_t* dAl = D0 + 128 * SSTR;
            uint32_t* dBh = D0 + 2 * 128 * SSTR;
            uint32_t* dBl = D0 + 3 * 128 * SSTR;
#pragma unroll
            for (int it = 0; it < 8; it++) {
                uint32_t h0, l0, h1, l1;
                cvt_pair(st[it].x, st[it].y, h0, l0);
                cvt_pair(st[it].z, st[it].w, h1, l1);
                uint32_t* dh = selT[it] ? dBh : dAh;
                uint32_t* dl = selT[it] ? dBl : dAl;
                int off = rowT[it] * SSTR + f4T[it] * 2;
                dh[off] = h0; dh[off + 1] = h1;
                dl[off] = l0; dl[off + 1] = l1;
            }
            if (ch + 2 < NCHUNK2) {
                int k0n = (ch + 2) * KC2;
#pragma unroll
                for (int it = 0; it < 8; it++) {
                    const float* src =
                        (selT[it] ? Wp : Ap) + (size_t)rowT[it] * ND + k0n + f4T[it] * 4;
                    st[it] = *(const float4*)src;
                }
            }
            __syncthreads();
        }
    }

    // Epilogue
#pragma unroll
    for (int nf = 0; nf < 4; nf++) {
        const int n = nBase + n0w + nf * 8 + q4 * 2;
        const float b0 = __ldg(g.bias + n);
        const float b1 = __ldg(g.bias + n + 1);
#pragma unroll
        for (int mf = 0; mf < 4; mf++) {
#pragma unroll
            for (int half = 0; half < 2; half++) {
                const int m = mBase + m0w + mf * 16 + r4 + half * 8;
                float v0 = (acc[mf][nf][half * 2] + b0) * g.scale;
                float v1 = (acc[mf][nf][half * 2 + 1] + b1) * g.scale;
                if (headmode) {
                    uint32_t hi, lo;
                    cvt_pair(v0, v1, hi, lo);
                    int b = m >> 11, s = m & (NS - 1);
                    int hh = n >> 6, e = n & 63;
                    size_t wo = (((size_t)((b * NH + hh) * NS + s)) * HDIM + e) >> 1;
                    g.Ph[wo] = hi;
                    g.Pl[wo] = lo;
                } else {
                    *(float2*)(g.C + (size_t)m * ND + n) = make_float2(v0, v1);
                }
            }
        }
    }
}

// ---------------------------------------------------------------------------
// Tensor-core flash attention, split-3 QK^T and PV, bf16 planes pre-converted.
// BQ=128 (8 warps x 16 rows), BKV=64, hd=64. Q pre-scaled (exp2-domain softmax).
// smem (u32): phase1 Qh[128*36] Ql[128*36]; phase2 Kh,Kl,Vh,Vl[64*36 each] + mask[64]
// ---------------------------------------------------------------------------
#define KSTR 36   // u32 words per row (144 B)

__global__ __launch_bounds__(256, 1) void attn_mma(const uint32_t* __restrict__ qh,
                                                   const uint32_t* __restrict__ ql,
                                                   const uint32_t* __restrict__ kh,
                                                   const uint32_t* __restrict__ kl,
                                                   const uint32_t* __restrict__ vh,
                                                   const uint32_t* __restrict__ vl,
                                                   const int* __restrict__ mask,
                                                   float* __restrict__ ctx)
{
    extern __shared__ uint32_t dynsm[];
    uint32_t* sKh = dynsm;                 // 64*36
    uint32_t* sKl = dynsm + 64 * KSTR;
    uint32_t* sVh = dynsm + 2 * 64 * KSTR;
    uint32_t* sVl = dynsm + 3 * 64 * KSTR;
    int*      sMk = (int*)(dynsm + 4 * 64 * KSTR);
    uint32_t* sQh = dynsm;                 // phase 1 only: 128*36
    uint32_t* sQl = dynsm + 128 * KSTR;

    const int tid = threadIdx.x;
    const int warp = tid >> 5;
    const int lane = tid & 31;
    const int r4 = lane >> 2, q4 = lane & 3;
    const int qt = blockIdx.x;     // 0..15
    const int bh = blockIdx.y;     // 0..31
    const int b = bh >> 4, h = bh & 15;
    const size_t headW = (size_t)bh * NS * (HDIM / 2);   // u32 words per head

    // ---- Phase 1: copy Q planes (pre-scaled bf16) to smem, load A-frags ----
    {
        const uint32_t* pQh = qh + headW + (size_t)qt * 128 * 32;
        const uint32_t* pQl = ql + headW + (size_t)qt * 128 * 32;
#pragma unroll
        for (int it = 0; it < 8; it++) {
            int g = tid + it * 256;        // 0..2047
            int pl = g >> 10;
            int gg = g & 1023;
            int row = gg >> 3, w4 = (gg & 7) * 4;
            uint4 v = *(const uint4*)((pl ? pQl : pQh) + row * 32 + w4);
            *(uint4*)((pl ? sQl : sQh) + row * KSTR + w4) = v;
        }
    }
    __syncthreads();

    uint32_t Qh[4][4], Ql[4][4];
#pragma unroll
    for (int kf = 0; kf < 4; kf++) {
        int off = (16 * warp + r4) * KSTR + 8 * kf + q4;
        Qh[kf][0] = sQh[off];              Qh[kf][1] = sQh[off + 8 * KSTR];
        Qh[kf][2] = sQh[off + 4];          Qh[kf][3] = sQh[off + 8 * KSTR + 4];
        Ql[kf][0] = sQl[off];              Ql[kf][1] = sQl[off + 8 * KSTR];
        Ql[kf][2] = sQl[off + 4];          Ql[kf][3] = sQl[off + 8 * KSTR + 4];
    }
    __syncthreads();   // Q region reusable as K/V

    // K-frag ldmatrix base: lanes 0-15 -> Khi (k+0 / k+8), 16-31 -> Klo
    const int sel = lane >> 3;
    const uint32_t kBase =
        smem_u32(sel < 2 ? sKh : sKl) + (uint32_t)((lane & 7) * 144 + (sel & 1) * 16);
    // V-frag ldmatrix base (trans): lanes 0-15 -> Vhi rows, 16-31 -> Vlo rows
    const uint32_t vBase = smem_u32(lane < 16 ? sVh : sVl) + (uint32_t)((lane & 15) * 144);

    float O[8][4];
    float mI0 = -INFINITY, mI1 = -INFINITY, lI0 = 0.f, lI1 = 0.f;
#pragma unroll
    for (int nf = 0; nf < 8; nf++)
#pragma unroll
        for (int c = 0; c < 4; c++) O[nf][c] = 0.f;

    // K/V copy mapping (8 uint4 groups per thread over 4 planes)
    const uint32_t* srcP[4] = {kh + headW, kl + headW, vh + headW, vl + headW};
    uint32_t* dstP[4] = {sKh, sKl, sVh, sVl};
    int srcOff[8]; uint32_t* dstA[8]; const uint32_t* srcA[8];
#pragma unroll
    for (int it = 0; it < 8; it++) {
        int g = tid + it * 256;            // 0..2047
        int pl = g >> 9;
        int gg = g & 511;
        int row = gg >> 3, w4 = (gg & 7) * 4;
        srcA[it] = srcP[pl];
        srcOff[it] = row * 32 + w4;
        dstA[it] = dstP[pl] + row * KSTR + w4;
    }
    const int* mrow = mask + (size_t)b * NS;

    uint4 stg[8];
    int mkld = 0;
#pragma unroll
    for (int it = 0; it < 8; it++)
        stg[it] = *(const uint4*)(srcA[it] + srcOff[it]);
    if (tid < 64) mkld = mrow[tid];

    for (int kt = 0; kt < NS / 64; kt++) {
        __syncthreads();   // previous tile's smem reads complete
#pragma unroll
        for (int it = 0; it < 8; it++)
            *(uint4*)(dstA[it]) = stg[it];
        if (tid < 64) sMk[tid] = mkld;
        __syncthreads();

        // prefetch next tile
        if (kt + 1 < NS / 64) {
            const size_t toff = (size_t)(kt + 1) * 2048;   // 64 rows * 32 words
#pragma unroll
            for (int it = 0; it < 8; it++)
                stg[it] = *(const uint4*)(srcA[it] + toff + srcOff[it]);
            if (tid < 64) mkld = mrow[(kt + 1) * 64 + tid];
        }

        // ---- S = Q K^T (split-3, K frags via ldmatrix.x4) ----
        float S[8][4];
#pragma unroll
        for (int nf = 0; nf < 8; nf++)
#pragma unroll
            for (int c = 0; c < 4; c++) S[nf][c] = 0.f;

#pragma unroll
        for (int kf = 0; kf < 4; kf++) {
#pragma unroll
            for (int nf = 0; nf < 8; nf++) {
                uint32_t kh2[2], kl2[2];
                ldsm_x4(kh2[0], kh2[1], kl2[0], kl2[1],
                        kBase + (uint32_t)(nf * 1152 + kf * 32));
                MMA16816(S[nf], Qh[kf], kh2);
                MMA16816(S[nf], Qh[kf], kl2);
                MMA16816(S[nf], Ql[kf], kh2);
            }
        }

        // ---- mask + online softmax (exp2 domain) ----
        float mt0 = -INFINITY, mt1 = -INFINITY;
#pragma unroll
        for (int nf = 0; nf < 8; nf++) {
            int c0 = 8 * nf + 2 * q4;
            if (sMk[c0])     { S[nf][0] = -9e9f; S[nf][2] = -9e9f; }
            if (sMk[c0 + 1]) { S[nf][1] = -9e9f; S[nf][3] = -9e9f; }
            mt0 = fmaxf(mt0, fmaxf(S[nf][0], S[nf][1]));
            mt1 = fmaxf(mt1, fmaxf(S[nf][2], S[nf][3]));
        }
        mt0 = fmaxf(mt0, __shfl_xor_sync(0xffffffffu, mt0, 1));
        mt0 = fmaxf(mt0, __shfl_xor_sync(0xffffffffu, mt0, 2));
        mt1 = fmaxf(mt1, __shfl_xor_sync(0xffffffffu, mt1, 1));
        mt1 = fmaxf(mt1, __shfl_xor_sync(0xffffffffu, mt1, 2));

        float mN0 = fmaxf(mI0, mt0), mN1 = fmaxf(mI1, mt1);
        float f0 = ex2f(mI0 - mN0), f1 = ex2f(mI1 - mN1);
        float rs0 = 0.f, rs1 = 0.f;
#pragma unroll
        for (int nf = 0; nf < 8; nf++) {
            S[nf][0] = ex2f(S[nf][0] - mN0);
            S[nf][1] = ex2f(S[nf][1] - mN0);
            S[nf][2] = ex2f(S[nf][2] - mN1);
            S[nf][3] = ex2f(S[nf][3] - mN1);
            rs0 += S[nf][0] + S[nf][1];
            rs1 += S[nf][2] + S[nf][3];
        }
        rs0 += __shfl_xor_sync(0xffffffffu, rs0, 1);
        rs0 += __shfl_xor_sync(0xffffffffu, rs0, 2);
        rs1 += __shfl_xor_sync(0xffffffffu, rs1, 1);
        rs1 += __shfl_xor_sync(0xffffffffu, rs1, 2);
        lI0 = lI0 * f0 + rs0;
        lI1 = lI1 * f1 + rs1;
        mI0 = mN0; mI1 = mN1;
#pragma unroll
        for (int nf = 0; nf < 8; nf++) {
            O[nf][0] *= f0; O[nf][1] *= f0;
            O[nf][2] *= f1; O[nf][3] *= f1;
        }

        // ---- repack P into split hi/lo A-frags ----
        uint32_t Ph[4][4], Pl[4][4];
#pragma unroll
        for (int kf = 0; kf < 4; kf++) {
            cvt_pair(S[2*kf][0],     S[2*kf][1],     Ph[kf][0], Pl[kf][0]);
            cvt_pair(S[2*kf][2],     S[2*kf][3],     Ph[kf][1], Pl[kf][1]);
            cvt_pair(S[2*kf + 1][0], S[2*kf + 1][1], Ph[kf][2], Pl[kf][2]);
            cvt_pair(S[2*kf + 1][2], S[2*kf + 1][3], Ph[kf][3], Pl[kf][3]);
        }

        // ---- O += P V (split-3; Vhi/Vlo frags in one ldmatrix.x4.trans) ----
#pragma unroll
        for (int kf = 0; kf < 4; kf++) {
            uint32_t abase = vBase + (uint32_t)(kf * 16 * 144);
#pragma unroll
            for (int nf = 0; nf < 8; nf++) {
                uint32_t vh2[2], vl2[2];
                ldsm_x4_t(vh2[0], vh2[1], vl2[0], vl2[1], abase + nf * 16);
                MMA16816(O[nf], Ph[kf], vh2);
                MMA16816(O[nf], Ph[kf], vl2);
                MMA16816(O[nf], Pl[kf], vh2);
            }
        }
    }

    // ---- normalize + write ctx [b][s][h*64+e] ----
    const float inv0 = 1.f / lI0;
    const float inv1 = 1.f / lI1;
    const int row0 = qt * 128 + 16 * warp + r4;
    float* op0 = ctx + ((size_t)(b * NS + row0)) * ND + h * HDIM + 2 * q4;
    float* op1 = ctx + ((size_t)(b * NS + row0 + 8)) * ND + h * HDIM + 2 * q4;
#pragma unroll
    for (int nf = 0; nf < 8; nf++) {
        *(float2*)(op0 + 8 * nf) = make_float2(O[nf][0] * inv0, O[nf][1] * inv0);
        *(float2*)(op1 + 8 * nf) = make_float2(O[nf][2] * inv1, O[nf][3] * inv1);
    }
}

extern "C" void kernel_launch(void* const* d_in, const int* in_sizes, int n_in,
                              void* d_out, int out_size)
{
    const float* q  = (const float*)d_in[0];
    const float* k  = (const float*)d_in[1];
    const float* v  = (const float*)d_in[2];
    const int* mask = (const int*)d_in[3];
    const float* Wq = (const float*)d_in[4];
    const float* bq = (const float*)d_in[5];
    const float* Wk = (const float*)d_in[6];
    const float* bk = (const float*)d_in[7];
    const float* Wv = (const float*)d_in[8];
    const float* bv = (const float*)d_in[9];
    const float* Wo = (const float*)d_in[10];
    const float* bo = (const float*)d_in[11];
    float* out = (float*)d_out;

    float* gctx_d;
    uint32_t *qh_d, *ql_d, *kh_d, *kl_d, *vh_d, *vl_d;
    cudaGetSymbolAddress((void**)&gctx_d, g_ctx);
    cudaGetSymbolAddress((void**)&qh_d, g_qh);
    cudaGetSymbolAddress((void**)&ql_d, g_ql);
    cudaGetSymbolAddress((void**)&kh_d, g_kh);
    cudaGetSymbolAddress((void**)&kl_d, g_kl);
    cudaGetSymbolAddress((void**)&vh_d, g_vh);
    cudaGetSymbolAddress((void**)&vl_d, g_vl);

    const int smem_gemm = 2 * STAGE_W * 4;            // 81920 B
    cudaFuncSetAttribute(gemm_mma, cudaFuncAttributeMaxDynamicSharedMemorySize, smem_gemm);
    const int smem_attn = (4 * 64 * KSTR + 64) * 4;   // 37120 B
    cudaFuncSetAttribute(attn_mma, cudaFuncAttributeMaxDynamicSharedMemorySize, smem_attn);

    // QKV projections: write bf16 hi/lo planes (Q pre-scaled)
    GArgs aq{q, Wq, bq, nullptr, qh_d, ql_d, QSCALE};
    GArgs ak{k, Wk, bk, nullptr, kh_d, kl_d, 1.f};
    GArgs av{v, Wv, bv, nullptr, vh_d, vl_d, 1.f};
    gemm_mma<<<dim3(ND / 128, MROWS / 128, 3), 256, smem_gemm>>>(aq, ak, av, 1);

    // attention (tensor cores, split-3, plane inputs)
    attn_mma<<<dim3(NS / 128, NB * NH), 256, smem_attn>>>(qh_d, ql_d, kh_d, kl_d,
                                                          vh_d, vl_d, mask, gctx_d);

    // output projection (fp32 in/out)
    GArgs ao{gctx_d, Wo, bo, out, nullptr, nullptr, 1.f};
    gemm_mma<<<dim3(ND / 128, MROWS / 128, 1), 256, smem_gemm>>>(ao, ao, ao, 0);
}